// round 11
// baseline (speedup 1.0000x reference)
#include <cuda_runtime.h>
#include <cuda_fp16.h>
#include <math.h>
#include <stdint.h>

#define NT 8192          // tokens (B*S)
#define ND 1024          // model dim
#define NE 8             // experts
#define NH 2816          // hidden dim
#define NROWS (NT * 2)   // total (token, expert-slot) rows
#define WELEM (NE * NH * ND)
#define NW4 (WELEM / 4)          // 5,767,168
#define NX4 (NT * ND / 4)        // 2,097,152 == 8192*256 exactly

// ---- device scratch (allocation-free) ----
__device__ int    g_counts[NE];
__device__ int    g_ctr[NE];
__device__ int    g_offsets[NE];
__device__ int    g_route_e[NROWS];
__device__ float  g_route_w[NROWS];
__device__ int    g_perm[NROWS];
__device__ float  g_pw[NROWS];
__device__ __half g_h[(size_t)NROWS * NH];
__device__ __half g_xh[(size_t)NT * ND];
__device__ __half g_w1h[(size_t)WELEM];
__device__ __half g_w3h[(size_t)WELEM];
__device__ __half g_w2h[(size_t)WELEM];

// ---------------------------------------------------------------------------
// helpers
// ---------------------------------------------------------------------------
__device__ __forceinline__ uint32_t smem_u32(const void* p) {
    uint32_t a;
    asm("{ .reg .u64 t; cvta.to.shared.u64 t, %1; cvt.u32.u64 %0, t; }" : "=r"(a) : "l"(p));
    return a;
}
__device__ __forceinline__ void mma_f16(float c[4], const uint32_t a[4], const uint32_t b[2]) {
    asm volatile(
        "mma.sync.aligned.m16n8k16.row.col.f32.f16.f16.f32 "
        "{%0,%1,%2,%3},{%4,%5,%6,%7},{%8,%9},{%0,%1,%2,%3};\n"
        : "+f"(c[0]), "+f"(c[1]), "+f"(c[2]), "+f"(c[3])
        : "r"(a[0]), "r"(a[1]), "r"(a[2]), "r"(a[3]), "r"(b[0]), "r"(b[1]));
}
__device__ __forceinline__ void ldsm_x4(uint32_t r[4], uint32_t addr) {
    asm volatile("ldmatrix.sync.aligned.m8n8.x4.shared.b16 {%0,%1,%2,%3}, [%4];"
        : "=r"(r[0]), "=r"(r[1]), "=r"(r[2]), "=r"(r[3]) : "r"(addr));
}
__device__ __forceinline__ void cpa16(uint32_t dst, const void* src, int bytes) {
    asm volatile("cp.async.cg.shared.global [%0], [%1], 16, %2;"
        :: "r"(dst), "l"(src), "r"(bytes) : "memory");
}
#define CPA_COMMIT() asm volatile("cp.async.commit_group;" ::: "memory")
#define CPA_WAIT1()  asm volatile("cp.async.wait_group 1;" ::: "memory")

// ---------------------------------------------------------------------------
// prep: one launch, 4 regions.
//   y==0: x fp32->fp16, zero out; blocks 0..1023 additionally run the router
//         (region 0 is scheduled first -> router overlaps weight conversion)
//   y==1/2/3: w1/w3/w2 fp32->fp16 (grid-stride)
// ---------------------------------------------------------------------------
__global__ void prep_kernel(const float4* __restrict__ x,
                            const float*  __restrict__ gwf,
                            const float4* __restrict__ w1,
                            const float4* __restrict__ w2,
                            const float4* __restrict__ w3,
                            float4* __restrict__ out) {
    __shared__ float sg[NE * ND];
    int tid  = threadIdx.x;
    int rgn  = blockIdx.y;
    int base = blockIdx.x * 256 + tid;

    if (rgn == 0) {
        // x convert + zero out (base < NX4 by construction: grid.x == 8192)
        {
            float4 v = x[base];
            out[base] = make_float4(0.f, 0.f, 0.f, 0.f);
            __half2 h0 = __floats2half2_rn(v.x, v.y);
            __half2 h1 = __floats2half2_rn(v.z, v.w);
            ((uint2*)g_xh)[base] = make_uint2(*(uint32_t*)&h0, *(uint32_t*)&h1);
        }
        if (blockIdx.x >= 1024) return;

        // ---- router (exact fp32, identical math to previous rounds) ----
        for (int i = tid; i < NE * ND / 4; i += 256)
            ((float4*)sg)[i] = ((const float4*)gwf)[i];
        __syncthreads();

        int lane = tid & 31;
        int t = blockIdx.x * 8 + (tid >> 5);

        const float4* xv = (const float4*)((const float*)x + (size_t)t * ND);
        float acc[NE];
#pragma unroll
        for (int e = 0; e < NE; e++) acc[e] = 0.f;
#pragma unroll
        for (int j = 0; j < ND / 128; j++) {
            int v = j * 32 + lane;
            float4 xx = xv[v];
#pragma unroll
            for (int e = 0; e < NE; e++) {
                float4 gg = ((const float4*)sg)[e * (ND / 4) + v];
                acc[e] += xx.x * gg.x + xx.y * gg.y + xx.z * gg.z + xx.w * gg.w;
            }
        }
#pragma unroll
        for (int e = 0; e < NE; e++)
#pragma unroll
            for (int o = 16; o > 0; o >>= 1)
                acc[e] += __shfl_xor_sync(0xffffffffu, acc[e], o);

        if (lane == 0) {
            int b0 = 0;
#pragma unroll
            for (int e = 1; e < NE; e++) if (acc[e] > acc[b0]) b0 = e;
            int b1 = (b0 == 0) ? 1 : 0;
#pragma unroll
            for (int e = 0; e < NE; e++)
                if (e != b0 && acc[e] > acc[b1]) b1 = e;
            float d  = acc[b1] - acc[b0];
            float e1 = expf(d);
            float s  = 1.f + e1;
            g_route_e[2 * t]     = b0;  g_route_w[2 * t]     = 1.f / s;
            g_route_e[2 * t + 1] = b1;  g_route_w[2 * t + 1] = e1 / s;
        }
        return;
    }

    const float4* src = (rgn == 1) ? w1 : (rgn == 2) ? w3 : w2;
    uint2* dst = (rgn == 1) ? (uint2*)g_w1h : (rgn == 2) ? (uint2*)g_w3h : (uint2*)g_w2h;
    for (int i = base; i < NW4; i += 8192 * 256) {
        float4 v = src[i];
        __half2 h0 = __floats2half2_rn(v.x, v.y);
        __half2 h1 = __floats2half2_rn(v.z, v.w);
        dst[i] = make_uint2(*(uint32_t*)&h0, *(uint32_t*)&h1);
    }
}

// ---------------------------------------------------------------------------
// scan: one block; histogram of route_e -> counts/offsets, zero g_ctr
// ---------------------------------------------------------------------------
__global__ void scan_kernel() {
    __shared__ int h[NE];
    int tid = threadIdx.x;
    if (tid < NE) h[tid] = 0;
    __syncthreads();
    for (int i = tid; i < NROWS; i += 256)
        atomicAdd(&h[g_route_e[i]], 1);
    __syncthreads();
    if (tid == 0) {
        int o = 0;
        for (int e = 0; e < NE; e++) {
            g_counts[e] = h[e];
            g_offsets[e] = o;
            o += h[e];
            g_ctr[e] = 0;
        }
    }
}

__global__ void scatter_kernel() {
    int i = blockIdx.x * blockDim.x + threadIdx.x;
    if (i >= NROWS) return;
    int e = g_route_e[i];
    int p = atomicAdd(&g_ctr[e], 1);
    int r = g_offsets[e] + p;
    g_perm[r] = i >> 1;
    g_pw[r]   = g_route_w[i];
}

// ---------------------------------------------------------------------------
// GEMM geometry: BK=64 halves; smem row = 72 halves (144 B; +16B/row shift
// keeps ldmatrix conflict-free); 3 cp.async stages
// ---------------------------------------------------------------------------
#define RS    144
#define ATILE (128 * RS)            // 18432 B
#define STAGE (2 * ATILE)           // 36864 B
#define GSMEM (3 * STAGE)           // 110592 B dynamic

// ---------------------------------------------------------------------------
// GEMM1: xh[gathered 128, 1024] @ {w1h,w3h}[64,1024]^T -> silu-gate -> g_h
// warps 4(m)x2(n); BK=64; cp.async 3-stage; ldmatrix frags
// ---------------------------------------------------------------------------
__global__ __launch_bounds__(256, 2) void gemm1_kernel() {
    extern __shared__ char dsm[];
    __shared__ int stok[128];

    int e   = blockIdx.z;
    int cnt = g_counts[e];
    int m0  = blockIdx.x * 128;          // m fastest -> B-slice L2 reuse
    if (m0 >= cnt) return;
    int n0  = blockIdx.y * 64;
    int off = g_offsets[e];

    int tid = threadIdx.x;
    if (tid < 128)
        stok[tid] = (m0 + tid < cnt) ? g_perm[off + m0 + tid] : -1;
    __syncthreads();

    const __half* w1e = g_w1h + (size_t)e * NH * ND;
    const __half* w3e = g_w3h + (size_t)e * NH * ND;

    int r  = tid >> 1;          // 0..127
    int hb = tid & 1;           // half-of-row (64B)
    int tok = stok[r];
    const __half* apt = (tok >= 0) ? (g_xh + (size_t)tok * ND + hb * 32) : g_xh;
    int ab = (tok >= 0) ? 16 : 0;
    const __half* bpt = (r < 64) ? (w1e + (size_t)(n0 + r) * ND + hb * 32)
                                 : (w3e + (size_t)(n0 + r - 64) * ND + hb * 32);

    uint32_t sbase = smem_u32(dsm);
    uint32_t dA = (uint32_t)(r * RS + hb * 64);

    int lane = tid & 31, wid = tid >> 5;
    int wm = wid >> 1, wn = wid & 1;
    int g = lane >> 2, t = lane & 3;

    uint32_t aOff = (uint32_t)((wm * 32 + (lane & 15)) * RS + (lane >> 4) * 16);
    uint32_t bOff = (uint32_t)(((lane & 7) + 8 * (lane >> 4)) * RS + ((lane >> 3) & 1) * 16)
                  + ATILE + (uint32_t)(wn * 32) * RS;

    float acc1[2][4][4], acc3[2][4][4];
#pragma unroll
    for (int mi = 0; mi < 2; mi++)
#pragma unroll
        for (int ni = 0; ni < 4; ni++)
#pragma unroll
            for (int q = 0; q < 4; q++) { acc1[mi][ni][q] = 0.f; acc3[mi][ni][q] = 0.f; }

    const int KT = ND / 64;   // 16

#pragma unroll
    for (int p = 0; p < 2; p++) {
        uint32_t st = sbase + p * STAGE;
        int ko = p * 64;
#pragma unroll
        for (int i = 0; i < 4; i++) {
            cpa16(st + dA + i * 16,         apt + ko + i * 8, ab);
            cpa16(st + ATILE + dA + i * 16, bpt + ko + i * 8, 16);
        }
        CPA_COMMIT();
    }

    for (int kt = 0; kt < KT; kt++) {
        CPA_WAIT1();
        __syncthreads();
        if (kt + 2 < KT) {
            uint32_t st = sbase + ((kt + 2) % 3) * STAGE;
            int ko = (kt + 2) * 64;
#pragma unroll
            for (int i = 0; i < 4; i++) {
                cpa16(st + dA + i * 16,         apt + ko + i * 8, ab);
                cpa16(st + ATILE + dA + i * 16, bpt + ko + i * 8, 16);
            }
        }
        CPA_COMMIT();

        uint32_t st = sbase + (kt % 3) * STAGE;
        uint32_t aAddr = st + aOff;
        uint32_t bAddr = st + bOff;
#pragma unroll
        for (int kc = 0; kc < 4; kc++) {
            uint32_t kb = kc * 32;
            uint32_t af[2][4], bf1[2][4], bf3[2][4];
            ldsm_x4(af[0], aAddr + kb);
            ldsm_x4(af[1], aAddr + kb + 16 * RS);
            ldsm_x4(bf1[0], bAddr + kb);
            ldsm_x4(bf1[1], bAddr + kb + 16 * RS);
            ldsm_x4(bf3[0], bAddr + kb + 64 * RS);
            ldsm_x4(bf3[1], bAddr + kb + 80 * RS);
#pragma unroll
            for (int mi = 0; mi < 2; mi++)
#pragma unroll
                for (int j = 0; j < 4; j++) {
                    mma_f16(acc1[mi][j], af[mi], &bf1[j >> 1][2 * (j & 1)]);
                    mma_f16(acc3[mi][j], af[mi], &bf3[j >> 1][2 * (j & 1)]);
                }
        }
    }

    // epilogue: silu(acc1)*acc3 -> half2 -> g_h
#pragma unroll
    for (int mi = 0; mi < 2; mi++) {
#pragma unroll
        for (int hf = 0; hf < 2; hf++) {
            int mrow = wm * 32 + mi * 16 + g + hf * 8;
            int m = m0 + mrow;
            if (m >= cnt) continue;
            size_t rr = (size_t)(off + m);
#pragma unroll
            for (int ni = 0; ni < 4; ni++) {
                float a0 = acc1[mi][ni][hf * 2 + 0];
                float a1 = acc1[mi][ni][hf * 2 + 1];
                float v0 = __fdividef(a0, 1.f + __expf(-a0)) * acc3[mi][ni][hf * 2 + 0];
                float v1 = __fdividef(a1, 1.f + __expf(-a1)) * acc3[mi][ni][hf * 2 + 1];
                int col = n0 + wn * 32 + ni * 8 + 2 * t;
                *(__half2*)(g_h + rr * NH + col) = __floats2half2_rn(v0, v1);
            }
        }
    }
}

// ---------------------------------------------------------------------------
// GEMM2: g_h[128, 2816] @ w2h[128, 2816]^T * pw -> atomicAdd out
// warps 2(m)x4(n); BK=64; cp.async 3-stage; ldmatrix frags
// ---------------------------------------------------------------------------
__global__ __launch_bounds__(256, 2) void gemm2_kernel(float* __restrict__ out) {
    extern __shared__ char dsm[];

    int e   = blockIdx.z;
    int cnt = g_counts[e];
    int m0  = blockIdx.y * 128;
    if (m0 >= cnt) return;
    int n0  = blockIdx.x * 128;          // n fastest -> A-slice L2 reuse
    int off = g_offsets[e];

    int tid = threadIdx.x;
    const __half* w2e = g_w2h + (size_t)e * ND * NH;

    int r  = tid >> 1;
    int hb = tid & 1;
    bool valid = (m0 + r) < cnt;
    const __half* apt = valid ? (g_h + (size_t)(off + m0 + r) * NH + hb * 32) : g_h;
    int ab = valid ? 16 : 0;
    const __half* bpt = w2e + (size_t)(n0 + r) * NH + hb * 32;

    uint32_t sbase = smem_u32(dsm);
    uint32_t dA = (uint32_t)(r * RS + hb * 64);

    int lane = tid & 31, wid = tid >> 5;
    int wm = wid >> 2, wn = wid & 3;
    int g = lane >> 2, t = lane & 3;

    uint32_t aOff = (uint32_t)((wm * 64 + (lane & 15)) * RS + (lane >> 4) * 16);
    uint32_t bOff = (uint32_t)(((lane & 7) + 8 * (lane >> 4)) * RS + ((lane >> 3) & 1) * 16)
                  + ATILE + (uint32_t)(wn * 32) * RS;

    float acc[4][4][4];
#pragma unroll
    for (int mi = 0; mi < 4; mi++)
#pragma unroll
        for (int ni = 0; ni < 4; ni++)
#pragma unroll
            for (int q = 0; q < 4; q++) acc[mi][ni][q] = 0.f;

    const int KT = NH / 64;   // 44

#pragma unroll
    for (int p = 0; p < 2; p++) {
        uint32_t st = sbase + p * STAGE;
        int ko = p * 64;
#pragma unroll
        for (int i = 0; i < 4; i++) {
            cpa16(st + dA + i * 16,         apt + ko + i * 8, ab);
            cpa16(st + ATILE + dA + i * 16, bpt + ko + i * 8, 16);
        }
        CPA_COMMIT();
    }

    for (int kt = 0; kt < KT; kt++) {
        CPA_WAIT1();
        __syncthreads();
        if (kt + 2 < KT) {
            uint32_t st = sbase + ((kt + 2) % 3) * STAGE;
            int ko = (kt + 2) * 64;
#pragma unroll
            for (int i = 0; i < 4; i++) {
                cpa16(st + dA + i * 16,         apt + ko + i * 8, ab);
                cpa16(st + ATILE + dA + i * 16, bpt + ko + i * 8, 16);
            }
        }
        CPA_COMMIT();

        uint32_t st = sbase + (kt % 3) * STAGE;
        uint32_t aAddr = st + aOff;
        uint32_t bAddr = st + bOff;
#pragma unroll
        for (int kc = 0; kc < 4; kc++) {
            uint32_t kb = kc * 32;
            uint32_t af[4][4], bf[2][4];
#pragma unroll
            for (int mi = 0; mi < 4; mi++)
                ldsm_x4(af[mi], aAddr + kb + (uint32_t)(mi * 16) * RS);
            ldsm_x4(bf[0], bAddr + kb);
            ldsm_x4(bf[1], bAddr + kb + 16 * RS);
#pragma unroll
            for (int mi = 0; mi < 4; mi++)
#pragma unroll
                for (int j = 0; j < 4; j++)
                    mma_f16(acc[mi][j], af[mi], &bf[j >> 1][2 * (j & 1)]);
        }
    }

    // epilogue: scale by combine weight, atomicAdd into out
#pragma unroll
    for (int mi = 0; mi < 4; mi++) {
#pragma unroll
        for (int hf = 0; hf < 2; hf++) {
            int mrow = wm * 64 + mi * 16 + g + hf * 8;
            int m = m0 + mrow;
            if (m >= cnt) continue;
            int rr = off + m;
            int tok = g_perm[rr];
            float w = g_pw[rr];
            float* orow = out + (size_t)tok * ND;
#pragma unroll
            for (int ni = 0; ni < 4; ni++) {
                int col = n0 + wn * 32 + ni * 8 + 2 * t;
                atomicAdd(orow + col,     w * acc[mi][ni][hf * 2 + 0]);
                atomicAdd(orow + col + 1, w * acc[mi][ni][hf * 2 + 1]);
            }
        }
    }
}

// ---------------------------------------------------------------------------
extern "C" void kernel_launch(void* const* d_in, const int* in_sizes, int n_in,
                              void* d_out, int out_size) {
    const float* x  = (const float*)d_in[0];
    const float* gw = (const float*)d_in[1];
    const float* w1 = (const float*)d_in[2];
    const float* w2 = (const float*)d_in[3];
    const float* w3 = (const float*)d_in[4];
    float* out = (float*)d_out;

    cudaFuncSetAttribute(gemm1_kernel, cudaFuncAttributeMaxDynamicSharedMemorySize, GSMEM);
    cudaFuncSetAttribute(gemm2_kernel, cudaFuncAttributeMaxDynamicSharedMemorySize, GSMEM);

    dim3 pg(8192, 4);   // y=0: x+router (first), y=1..3: w1/w3/w2 grid-stride
    prep_kernel<<<pg, 256>>>((const float4*)x, gw, (const float4*)w1,
                             (const float4*)w2, (const float4*)w3, (float4*)out);
    scan_kernel<<<1, 256>>>();
    scatter_kernel<<<(NROWS + 255) / 256, 256>>>();

    dim3 g1(NROWS / 128, NH / 64, NE);   // m fastest; (128, 44, 8)
    gemm1_kernel<<<g1, 256, GSMEM>>>();

    dim3 g2(ND / 128, NROWS / 128, NE);  // n fastest; (8, 128, 8)
    gemm2_kernel<<<g2, 256, GSMEM>>>(out);
}

// round 12
// speedup vs baseline: 1.4104x; 1.4104x over previous
#include <cuda_runtime.h>
#include <cuda_fp16.h>
#include <math.h>
#include <stdint.h>

#define NT 8192          // tokens (B*S)
#define ND 1024          // model dim
#define NE 8             // experts
#define NH 2816          // hidden dim
#define NROWS (NT * 2)   // total (token, expert-slot) rows
#define WELEM (NE * NH * ND)
#define NW4 (WELEM / 4)          // 5,767,168
#define NX4 (NT * ND / 4)        // 2,097,152 == 8192*256 exactly

// ---- device scratch (allocation-free) ----
__device__ int    g_counts[NE];
__device__ int    g_ctr[NE];
__device__ int    g_offsets[NE];
__device__ int    g_route_e[NROWS];
__device__ float  g_route_w[NROWS];
__device__ int    g_perm[NROWS];
__device__ float  g_pw[NROWS];
__device__ __half g_h[(size_t)NROWS * NH];
__device__ __half g_xh[(size_t)NT * ND];
__device__ __half g_w1h[(size_t)WELEM];
__device__ __half g_w3h[(size_t)WELEM];
__device__ __half g_w2h[(size_t)WELEM];

// ---------------------------------------------------------------------------
// helpers
// ---------------------------------------------------------------------------
__device__ __forceinline__ uint32_t smem_u32(const void* p) {
    uint32_t a;
    asm("{ .reg .u64 t; cvta.to.shared.u64 t, %1; cvt.u32.u64 %0, t; }" : "=r"(a) : "l"(p));
    return a;
}
__device__ __forceinline__ void mma_f16(float c[4], const uint32_t a[4], const uint32_t b[2]) {
    asm volatile(
        "mma.sync.aligned.m16n8k16.row.col.f32.f16.f16.f32 "
        "{%0,%1,%2,%3},{%4,%5,%6,%7},{%8,%9},{%0,%1,%2,%3};\n"
        : "+f"(c[0]), "+f"(c[1]), "+f"(c[2]), "+f"(c[3])
        : "r"(a[0]), "r"(a[1]), "r"(a[2]), "r"(a[3]), "r"(b[0]), "r"(b[1]));
}
__device__ __forceinline__ void ldsm_x4(uint32_t r[4], uint32_t addr) {
    asm volatile("ldmatrix.sync.aligned.m8n8.x4.shared.b16 {%0,%1,%2,%3}, [%4];"
        : "=r"(r[0]), "=r"(r[1]), "=r"(r[2]), "=r"(r[3]) : "r"(addr));
}
__device__ __forceinline__ void cpa16(uint32_t dst, const void* src, int bytes) {
    asm volatile("cp.async.cg.shared.global [%0], [%1], 16, %2;"
        :: "r"(dst), "l"(src), "r"(bytes) : "memory");
}
#define CPA_COMMIT() asm volatile("cp.async.commit_group;" ::: "memory")
#define CPA_WAIT2()  asm volatile("cp.async.wait_group 2;" ::: "memory")

// ---------------------------------------------------------------------------
// prep: one launch, 4 regions.
//   y==0: x fp32->fp16, zero out; blocks 0..1023 additionally run the router
//   y==1/2/3: w1/w3/w2 fp32->fp16 (grid-stride)
// ---------------------------------------------------------------------------
__global__ void prep_kernel(const float4* __restrict__ x,
                            const float*  __restrict__ gwf,
                            const float4* __restrict__ w1,
                            const float4* __restrict__ w2,
                            const float4* __restrict__ w3,
                            float4* __restrict__ out) {
    __shared__ float sg[NE * ND];
    int tid  = threadIdx.x;
    int rgn  = blockIdx.y;
    int base = blockIdx.x * 256 + tid;

    if (rgn == 0) {
        {
            float4 v = x[base];
            out[base] = make_float4(0.f, 0.f, 0.f, 0.f);
            __half2 h0 = __floats2half2_rn(v.x, v.y);
            __half2 h1 = __floats2half2_rn(v.z, v.w);
            ((uint2*)g_xh)[base] = make_uint2(*(uint32_t*)&h0, *(uint32_t*)&h1);
        }
        if (blockIdx.x >= 1024) return;

        // ---- router (exact fp32, identical math to previous rounds) ----
        for (int i = tid; i < NE * ND / 4; i += 256)
            ((float4*)sg)[i] = ((const float4*)gwf)[i];
        __syncthreads();

        int lane = tid & 31;
        int t = blockIdx.x * 8 + (tid >> 5);

        const float4* xv = (const float4*)((const float*)x + (size_t)t * ND);
        float acc[NE];
#pragma unroll
        for (int e = 0; e < NE; e++) acc[e] = 0.f;
#pragma unroll
        for (int j = 0; j < ND / 128; j++) {
            int v = j * 32 + lane;
            float4 xx = xv[v];
#pragma unroll
            for (int e = 0; e < NE; e++) {
                float4 gg = ((const float4*)sg)[e * (ND / 4) + v];
                acc[e] += xx.x * gg.x + xx.y * gg.y + xx.z * gg.z + xx.w * gg.w;
            }
        }
#pragma unroll
        for (int e = 0; e < NE; e++)
#pragma unroll
            for (int o = 16; o > 0; o >>= 1)
                acc[e] += __shfl_xor_sync(0xffffffffu, acc[e], o);

        if (lane == 0) {
            int b0 = 0;
#pragma unroll
            for (int e = 1; e < NE; e++) if (acc[e] > acc[b0]) b0 = e;
            int b1 = (b0 == 0) ? 1 : 0;
#pragma unroll
            for (int e = 0; e < NE; e++)
                if (e != b0 && acc[e] > acc[b1]) b1 = e;
            float d  = acc[b1] - acc[b0];
            float e1 = expf(d);
            float s  = 1.f + e1;
            g_route_e[2 * t]     = b0;  g_route_w[2 * t]     = 1.f / s;
            g_route_e[2 * t + 1] = b1;  g_route_w[2 * t + 1] = e1 / s;
        }
        return;
    }

    const float4* src = (rgn == 1) ? w1 : (rgn == 2) ? w3 : w2;
    uint2* dst = (rgn == 1) ? (uint2*)g_w1h : (rgn == 2) ? (uint2*)g_w3h : (uint2*)g_w2h;
    for (int i = base; i < NW4; i += 8192 * 256) {
        float4 v = src[i];
        __half2 h0 = __floats2half2_rn(v.x, v.y);
        __half2 h1 = __floats2half2_rn(v.z, v.w);
        dst[i] = make_uint2(*(uint32_t*)&h0, *(uint32_t*)&h1);
    }
}

// ---------------------------------------------------------------------------
// scan: one block; histogram of route_e -> counts/offsets, zero g_ctr
// ---------------------------------------------------------------------------
__global__ void scan_kernel() {
    __shared__ int h[NE];
    int tid = threadIdx.x;
    if (tid < NE) h[tid] = 0;
    __syncthreads();
    for (int i = tid; i < NROWS; i += 256)
        atomicAdd(&h[g_route_e[i]], 1);
    __syncthreads();
    if (tid == 0) {
        int o = 0;
        for (int e = 0; e < NE; e++) {
            g_counts[e] = h[e];
            g_offsets[e] = o;
            o += h[e];
            g_ctr[e] = 0;
        }
    }
}

__global__ void scatter_kernel() {
    int i = blockIdx.x * blockDim.x + threadIdx.x;
    if (i >= NROWS) return;
    int e = g_route_e[i];
    int p = atomicAdd(&g_ctr[e], 1);
    int r = g_offsets[e] + p;
    g_perm[r] = i >> 1;
    g_pw[r]   = g_route_w[i];
}

// ---------------------------------------------------------------------------
// GEMM geometry (R9-proven): BK=32 halves, row stride 80 B, FOUR cp.async
// stages (prefetch distance 3 covers L2 latency), 2 CTAs/SM
// ---------------------------------------------------------------------------
#define RS    80
#define ATILE (128 * RS)            // 10240 B
#define STAGE (2 * ATILE)           // 20480 B
#define GSMEM (4 * STAGE)           // 81920 B dynamic; x2 CTA = 160 KB < 228 KB

// ---------------------------------------------------------------------------
// GEMM1: xh[gathered 128, 1024] @ {w1h,w3h}[64,1024]^T -> silu-gate -> g_h
// warps 4(m)x2(n); cp.async 4-stage; ldmatrix frags
// ---------------------------------------------------------------------------
__global__ __launch_bounds__(256, 2) void gemm1_kernel() {
    extern __shared__ char dsm[];
    __shared__ int stok[128];

    int e   = blockIdx.z;
    int cnt = g_counts[e];
    int m0  = blockIdx.x * 128;          // m fastest -> B-slice L2 reuse
    if (m0 >= cnt) return;
    int n0  = blockIdx.y * 64;
    int off = g_offsets[e];

    int tid = threadIdx.x;
    if (tid < 128)
        stok[tid] = (m0 + tid < cnt) ? g_perm[off + m0 + tid] : -1;
    __syncthreads();

    const __half* w1e = g_w1h + (size_t)e * NH * ND;
    const __half* w3e = g_w3h + (size_t)e * NH * ND;

    int r  = tid >> 2;          // 0..63
    int ch = tid & 3;           // 16B chunk
    const __half* ap[2]; int abytes[2];
#pragma unroll
    for (int i = 0; i < 2; i++) {
        int tok = stok[r + 64 * i];
        ap[i]     = (tok >= 0) ? (g_xh + (size_t)tok * ND + ch * 8) : g_xh;
        abytes[i] = (tok >= 0) ? 16 : 0;
    }
    const __half* bp0 = w1e + (size_t)(n0 + r) * ND + ch * 8;
    const __half* bp1 = w3e + (size_t)(n0 + r) * ND + ch * 8;

    uint32_t sbase = smem_u32(dsm);
    uint32_t dA0 = (uint32_t)(r * RS + ch * 16);
    uint32_t dA1 = (uint32_t)((r + 64) * RS + ch * 16);

    int lane = tid & 31, wid = tid >> 5;
    int wm = wid >> 1, wn = wid & 1;
    int g = lane >> 2, t = lane & 3;

    uint32_t aOff = (uint32_t)((wm * 32 + (lane & 15)) * RS + (lane >> 4) * 16);
    uint32_t bOff = (uint32_t)(((lane & 7) + 8 * (lane >> 4)) * RS + ((lane >> 3) & 1) * 16)
                  + ATILE + (uint32_t)(wn * 32) * RS;

    float acc1[2][4][4], acc3[2][4][4];
#pragma unroll
    for (int mi = 0; mi < 2; mi++)
#pragma unroll
        for (int ni = 0; ni < 4; ni++)
#pragma unroll
            for (int q = 0; q < 4; q++) { acc1[mi][ni][q] = 0.f; acc3[mi][ni][q] = 0.f; }

    const int KT = ND / 32;   // 32

    // prefill stages 0,1,2
#pragma unroll
    for (int p = 0; p < 3; p++) {
        uint32_t st = sbase + p * STAGE;
        int ko = p * 32;
        cpa16(st + dA0, ap[0] + ko, abytes[0]);
        cpa16(st + dA1, ap[1] + ko, abytes[1]);
        cpa16(st + ATILE + dA0, bp0 + ko, 16);
        cpa16(st + ATILE + dA1, bp1 + ko, 16);
        CPA_COMMIT();
    }

    for (int kt = 0; kt < KT; kt++) {
        CPA_WAIT2();
        __syncthreads();
        if (kt + 3 < KT) {
            uint32_t st = sbase + ((kt + 3) & 3) * STAGE;
            int ko = (kt + 3) * 32;
            cpa16(st + dA0, ap[0] + ko, abytes[0]);
            cpa16(st + dA1, ap[1] + ko, abytes[1]);
            cpa16(st + ATILE + dA0, bp0 + ko, 16);
            cpa16(st + ATILE + dA1, bp1 + ko, 16);
        }
        CPA_COMMIT();

        uint32_t st = sbase + (kt & 3) * STAGE;
        uint32_t aAddr = st + aOff;
        uint32_t bAddr = st + bOff;
#pragma unroll
        for (int kc = 0; kc < 2; kc++) {
            uint32_t kb = kc * 32;
            uint32_t af[2][4], bf1[2][4], bf3[2][4];
            ldsm_x4(af[0], aAddr + kb);
            ldsm_x4(af[1], aAddr + kb + 16 * RS);
            ldsm_x4(bf1[0], bAddr + kb);
            ldsm_x4(bf1[1], bAddr + kb + 16 * RS);
            ldsm_x4(bf3[0], bAddr + kb + 64 * RS);
            ldsm_x4(bf3[1], bAddr + kb + 80 * RS);
#pragma unroll
            for (int mi = 0; mi < 2; mi++)
#pragma unroll
                for (int j = 0; j < 4; j++) {
                    mma_f16(acc1[mi][j], af[mi], &bf1[j >> 1][2 * (j & 1)]);
                    mma_f16(acc3[mi][j], af[mi], &bf3[j >> 1][2 * (j & 1)]);
                }
        }
    }

    // epilogue: silu(acc1)*acc3 -> half2 -> g_h
#pragma unroll
    for (int mi = 0; mi < 2; mi++) {
#pragma unroll
        for (int hf = 0; hf < 2; hf++) {
            int mrow = wm * 32 + mi * 16 + g + hf * 8;
            int m = m0 + mrow;
            if (m >= cnt) continue;
            size_t rr = (size_t)(off + m);
#pragma unroll
            for (int ni = 0; ni < 4; ni++) {
                float a0 = acc1[mi][ni][hf * 2 + 0];
                float a1 = acc1[mi][ni][hf * 2 + 1];
                float v0 = __fdividef(a0, 1.f + __expf(-a0)) * acc3[mi][ni][hf * 2 + 0];
                float v1 = __fdividef(a1, 1.f + __expf(-a1)) * acc3[mi][ni][hf * 2 + 1];
                int col = n0 + wn * 32 + ni * 8 + 2 * t;
                *(__half2*)(g_h + rr * NH + col) = __floats2half2_rn(v0, v1);
            }
        }
    }
}

// ---------------------------------------------------------------------------
// GEMM2: g_h[128, 2816] @ w2h[128, 2816]^T * pw -> atomicAdd out
// warps 2(m)x4(n); cp.async 4-stage; ldmatrix frags
// ---------------------------------------------------------------------------
__global__ __launch_bounds__(256, 2) void gemm2_kernel(float* __restrict__ out) {
    extern __shared__ char dsm[];

    int e   = blockIdx.z;
    int cnt = g_counts[e];
    int m0  = blockIdx.y * 128;
    if (m0 >= cnt) return;
    int n0  = blockIdx.x * 128;          // n fastest -> A-slice L2 reuse
    int off = g_offsets[e];

    int tid = threadIdx.x;
    const __half* w2e = g_w2h + (size_t)e * ND * NH;

    int r  = tid >> 2;
    int ch = tid & 3;
    const __half* ap[2]; int abytes[2];
#pragma unroll
    for (int i = 0; i < 2; i++) {
        bool valid = (m0 + r + 64 * i) < cnt;
        ap[i]     = valid ? (g_h + (size_t)(off + m0 + r + 64 * i) * NH + ch * 8) : g_h;
        abytes[i] = valid ? 16 : 0;
    }
    const __half* bp[2];
#pragma unroll
    for (int i = 0; i < 2; i++)
        bp[i] = w2e + (size_t)(n0 + r + 64 * i) * NH + ch * 8;

    uint32_t sbase = smem_u32(dsm);
    uint32_t dA0 = (uint32_t)(r * RS + ch * 16);
    uint32_t dA1 = (uint32_t)((r + 64) * RS + ch * 16);

    int lane = tid & 31, wid = tid >> 5;
    int wm = wid >> 2, wn = wid & 3;
    int g = lane >> 2, t = lane & 3;

    uint32_t aOff = (uint32_t)((wm * 64 + (lane & 15)) * RS + (lane >> 4) * 16);
    uint32_t bOff = (uint32_t)(((lane & 7) + 8 * (lane >> 4)) * RS + ((lane >> 3) & 1) * 16)
                  + ATILE + (uint32_t)(wn * 32) * RS;

    float acc[4][4][4];
#pragma unroll
    for (int mi = 0; mi < 4; mi++)
#pragma unroll
        for (int ni = 0; ni < 4; ni++)
#pragma unroll
            for (int q = 0; q < 4; q++) acc[mi][ni][q] = 0.f;

    const int KT = NH / 32;   // 88

#pragma unroll
    for (int p = 0; p < 3; p++) {
        uint32_t st = sbase + p * STAGE;
        int ko = p * 32;
        cpa16(st + dA0, ap[0] + ko, abytes[0]);
        cpa16(st + dA1, ap[1] + ko, abytes[1]);
        cpa16(st + ATILE + dA0, bp[0] + ko, 16);
        cpa16(st + ATILE + dA1, bp[1] + ko, 16);
        CPA_COMMIT();
    }

    for (int kt = 0; kt < KT; kt++) {
        CPA_WAIT2();
        __syncthreads();
        if (kt + 3 < KT) {
            uint32_t st = sbase + ((kt + 3) & 3) * STAGE;
            int ko = (kt + 3) * 32;
            cpa16(st + dA0, ap[0] + ko, abytes[0]);
            cpa16(st + dA1, ap[1] + ko, abytes[1]);
            cpa16(st + ATILE + dA0, bp[0] + ko, 16);
            cpa16(st + ATILE + dA1, bp[1] + ko, 16);
        }
        CPA_COMMIT();

        uint32_t st = sbase + (kt & 3) * STAGE;
        uint32_t aAddr = st + aOff;
        uint32_t bAddr = st + bOff;
#pragma unroll
        for (int kc = 0; kc < 2; kc++) {
            uint32_t kb = kc * 32;
            uint32_t af[4][4], bf[2][4];
#pragma unroll
            for (int mi = 0; mi < 4; mi++)
                ldsm_x4(af[mi], aAddr + kb + (uint32_t)(mi * 16) * RS);
            ldsm_x4(bf[0], bAddr + kb);
            ldsm_x4(bf[1], bAddr + kb + 16 * RS);
#pragma unroll
            for (int mi = 0; mi < 4; mi++)
#pragma unroll
                for (int j = 0; j < 4; j++)
                    mma_f16(acc[mi][j], af[mi], &bf[j >> 1][2 * (j & 1)]);
        }
    }

    // epilogue: scale by combine weight, atomicAdd into out
#pragma unroll
    for (int mi = 0; mi < 4; mi++) {
#pragma unroll
        for (int hf = 0; hf < 2; hf++) {
            int mrow = wm * 64 + mi * 16 + g + hf * 8;
            int m = m0 + mrow;
            if (m >= cnt) continue;
            int rr = off + m;
            int tok = g_perm[rr];
            float w = g_pw[rr];
            float* orow = out + (size_t)tok * ND;
#pragma unroll
            for (int ni = 0; ni < 4; ni++) {
                int col = n0 + wn * 32 + ni * 8 + 2 * t;
                atomicAdd(orow + col,     w * acc[mi][ni][hf * 2 + 0]);
                atomicAdd(orow + col + 1, w * acc[mi][ni][hf * 2 + 1]);
            }
        }
    }
}

// ---------------------------------------------------------------------------
extern "C" void kernel_launch(void* const* d_in, const int* in_sizes, int n_in,
                              void* d_out, int out_size) {
    const float* x  = (const float*)d_in[0];
    const float* gw = (const float*)d_in[1];
    const float* w1 = (const float*)d_in[2];
    const float* w2 = (const float*)d_in[3];
    const float* w3 = (const float*)d_in[4];
    float* out = (float*)d_out;

    cudaFuncSetAttribute(gemm1_kernel, cudaFuncAttributeMaxDynamicSharedMemorySize, GSMEM);
    cudaFuncSetAttribute(gemm2_kernel, cudaFuncAttributeMaxDynamicSharedMemorySize, GSMEM);

    dim3 pg(8192, 4);   // y=0: x+router (first), y=1..3: w1/w3/w2 grid-stride
    prep_kernel<<<pg, 256>>>((const float4*)x, gw, (const float4*)w1,
                             (const float4*)w2, (const float4*)w3, (float4*)out);
    scan_kernel<<<1, 256>>>();
    scatter_kernel<<<(NROWS + 255) / 256, 256>>>();

    dim3 g1(NROWS / 128, NH / 64, NE);   // m fastest; (128, 44, 8)
    gemm1_kernel<<<g1, 256, GSMEM>>>();

    dim3 g2(ND / 128, NROWS / 128, NE);  // n fastest; (8, 128, 8)
    gemm2_kernel<<<g2, 256, GSMEM>>>(out);
}

// round 14
// speedup vs baseline: 1.4555x; 1.0320x over previous
#include <cuda_runtime.h>
#include <cuda_fp16.h>
#include <math.h>
#include <stdint.h>

#define NT 8192          // tokens (B*S)
#define ND 1024          // model dim
#define NE 8             // experts
#define NH 2816          // hidden dim
#define NROWS (NT * 2)   // total (token, expert-slot) rows
#define WELEM (NE * NH * ND)
#define NW4 (WELEM / 4)          // 5,767,168
#define NX4 (NT * ND / 4)        // 2,097,152 == 8192*256 exactly
#define MAXTILES 144

// ---- device scratch (allocation-free) ----
__device__ int    g_counts[NE];
__device__ int    g_ctr[NE];
__device__ int    g_offsets[NE];
__device__ int    g_route_e[NROWS];
__device__ float  g_route_w[NROWS];
__device__ int    g_perm[NROWS];
__device__ float  g_pw[NROWS];
__device__ int    g_ntiles;
__device__ int    g_tile_e[MAXTILES];
__device__ int    g_tile_m0[MAXTILES];
__device__ __half g_h[(size_t)NROWS * NH];
__device__ __half g_xh[(size_t)NT * ND];
__device__ __half g_w1h[(size_t)WELEM];
__device__ __half g_w3h[(size_t)WELEM];
__device__ __half g_w2h[(size_t)WELEM];

// ---------------------------------------------------------------------------
// helpers
// ---------------------------------------------------------------------------
__device__ __forceinline__ uint32_t smem_u32(const void* p) {
    uint32_t a;
    asm("{ .reg .u64 t; cvta.to.shared.u64 t, %1; cvt.u32.u64 %0, t; }" : "=r"(a) : "l"(p));
    return a;
}
__device__ __forceinline__ void mma_f16(float c[4], const uint32_t a[4], const uint32_t b[2]) {
    asm volatile(
        "mma.sync.aligned.m16n8k16.row.col.f32.f16.f16.f32 "
        "{%0,%1,%2,%3},{%4,%5,%6,%7},{%8,%9},{%0,%1,%2,%3};\n"
        : "+f"(c[0]), "+f"(c[1]), "+f"(c[2]), "+f"(c[3])
        : "r"(a[0]), "r"(a[1]), "r"(a[2]), "r"(a[3]), "r"(b[0]), "r"(b[1]));
}
__device__ __forceinline__ void ldsm_x4(uint32_t r[4], uint32_t addr) {
    asm volatile("ldmatrix.sync.aligned.m8n8.x4.shared.b16 {%0,%1,%2,%3}, [%4];"
        : "=r"(r[0]), "=r"(r[1]), "=r"(r[2]), "=r"(r[3]) : "r"(addr));
}
__device__ __forceinline__ void cpa16(uint32_t dst, const void* src, int bytes) {
    asm volatile("cp.async.cg.shared.global [%0], [%1], 16, %2;"
        :: "r"(dst), "l"(src), "r"(bytes) : "memory");
}
#define CPA_COMMIT() asm volatile("cp.async.commit_group;" ::: "memory")
#define CPA_WAIT2()  asm volatile("cp.async.wait_group 2;" ::: "memory")

// ---------------------------------------------------------------------------
// prep: one launch, 4 regions.
//   y==0: x fp32->fp16, zero out; blocks 0..1023 additionally run the router
//   y==1/2/3: w1/w3/w2 fp32->fp16 (grid-stride)
// ---------------------------------------------------------------------------
__global__ void prep_kernel(const float4* __restrict__ x,
                            const float*  __restrict__ gwf,
                            const float4* __restrict__ w1,
                            const float4* __restrict__ w2,
                            const float4* __restrict__ w3,
                            float4* __restrict__ out) {
    __shared__ float sg[NE * ND];
    int tid  = threadIdx.x;
    int rgn  = blockIdx.y;
    int base = blockIdx.x * 256 + tid;

    if (rgn == 0) {
        {
            float4 v = x[base];
            out[base] = make_float4(0.f, 0.f, 0.f, 0.f);
            __half2 h0 = __floats2half2_rn(v.x, v.y);
            __half2 h1 = __floats2half2_rn(v.z, v.w);
            ((uint2*)g_xh)[base] = make_uint2(*(uint32_t*)&h0, *(uint32_t*)&h1);
        }
        if (blockIdx.x >= 1024) return;

        // ---- router (exact fp32, identical math to previous rounds) ----
        for (int i = tid; i < NE * ND / 4; i += 256)
            ((float4*)sg)[i] = ((const float4*)gwf)[i];
        __syncthreads();

        int lane = tid & 31;
        int t = blockIdx.x * 8 + (tid >> 5);

        const float4* xv = (const float4*)((const float*)x + (size_t)t * ND);
        float acc[NE];
#pragma unroll
        for (int e = 0; e < NE; e++) acc[e] = 0.f;
#pragma unroll
        for (int j = 0; j < ND / 128; j++) {
            int v = j * 32 + lane;
            float4 xx = xv[v];
#pragma unroll
            for (int e = 0; e < NE; e++) {
                float4 gg = ((const float4*)sg)[e * (ND / 4) + v];
                acc[e] += xx.x * gg.x + xx.y * gg.y + xx.z * gg.z + xx.w * gg.w;
            }
        }
#pragma unroll
        for (int e = 0; e < NE; e++)
#pragma unroll
            for (int o = 16; o > 0; o >>= 1)
                acc[e] += __shfl_xor_sync(0xffffffffu, acc[e], o);

        if (lane == 0) {
            int b0 = 0;
#pragma unroll
            for (int e = 1; e < NE; e++) if (acc[e] > acc[b0]) b0 = e;
            int b1 = (b0 == 0) ? 1 : 0;
#pragma unroll
            for (int e = 0; e < NE; e++)
                if (e != b0 && acc[e] > acc[b1]) b1 = e;
            float d  = acc[b1] - acc[b0];
            float e1 = expf(d);
            float s  = 1.f + e1;
            g_route_e[2 * t]     = b0;  g_route_w[2 * t]     = 1.f / s;
            g_route_e[2 * t + 1] = b1;  g_route_w[2 * t + 1] = e1 / s;
        }
        return;
    }

    const float4* src = (rgn == 1) ? w1 : (rgn == 2) ? w3 : w2;
    uint2* dst = (rgn == 1) ? (uint2*)g_w1h : (rgn == 2) ? (uint2*)g_w3h : (uint2*)g_w2h;
    for (int i = base; i < NW4; i += 8192 * 256) {
        float4 v = src[i];
        __half2 h0 = __floats2half2_rn(v.x, v.y);
        __half2 h1 = __floats2half2_rn(v.z, v.w);
        dst[i] = make_uint2(*(uint32_t*)&h0, *(uint32_t*)&h1);
    }
}

// ---------------------------------------------------------------------------
// scan: one block; histogram of route_e -> counts/offsets, zero g_ctr,
// and build the compact active-tile table (<=135 tiles of 128 rows)
// ---------------------------------------------------------------------------
__global__ void scan_kernel() {
    __shared__ int h[NE];
    int tid = threadIdx.x;
    if (tid < NE) h[tid] = 0;
    __syncthreads();
    for (int i = tid; i < NROWS; i += 256)
        atomicAdd(&h[g_route_e[i]], 1);
    __syncthreads();
    if (tid == 0) {
        int o = 0, nt = 0;
        for (int e = 0; e < NE; e++) {
            int c = h[e];
            g_counts[e] = c;
            g_offsets[e] = o;
            o += c;
            g_ctr[e] = 0;
            for (int m0 = 0; m0 < c; m0 += 128) {
                g_tile_e[nt]  = e;
                g_tile_m0[nt] = m0;
                nt++;
            }
        }
        g_ntiles = nt;
    }
}

__global__ void scatter_kernel() {
    int i = blockIdx.x * blockDim.x + threadIdx.x;
    if (i >= NROWS) return;
    int e = g_route_e[i];
    int p = atomicAdd(&g_ctr[e], 1);
    int r = g_offsets[e] + p;
    g_perm[r] = i >> 1;
    g_pw[r]   = g_route_w[i];
}

// ---------------------------------------------------------------------------
// GEMM geometry: BK=32 halves, row stride 80 B, FOUR cp.async stages
// ---------------------------------------------------------------------------
#define RS    80
#define ATILE (128 * RS)            // 10240 B
#define STAGE (2 * ATILE)           // 20480 B
#define GSMEM (4 * STAGE)           // 81920 B dynamic; x2 CTA = 160 KB < 228 KB

// ---------------------------------------------------------------------------
// GEMM1: xh[gathered 128, 1024] @ {w1h,w3h}[64,1024]^T -> silu-gate -> g_h
// grid (MAXTILES, 44): x = compact m-tile (fastest -> B-slice L2 reuse)
// ---------------------------------------------------------------------------
__global__ __launch_bounds__(256, 2) void gemm1_kernel() {
    extern __shared__ char dsm[];
    __shared__ int stok[128];

    int bx = blockIdx.x;
    if (bx >= g_ntiles) return;
    int e   = g_tile_e[bx];
    int m0  = g_tile_m0[bx];
    int cnt = g_counts[e];
    int n0  = blockIdx.y * 64;
    int off = g_offsets[e];

    int tid = threadIdx.x;
    if (tid < 128)
        stok[tid] = (m0 + tid < cnt) ? g_perm[off + m0 + tid] : -1;
    __syncthreads();

    const __half* w1e = g_w1h + (size_t)e * NH * ND;
    const __half* w3e = g_w3h + (size_t)e * NH * ND;

    int r  = tid >> 2;          // 0..63
    int ch = tid & 3;           // 16B chunk
    const __half* ap[2]; int abytes[2];
#pragma unroll
    for (int i = 0; i < 2; i++) {
        int tok = stok[r + 64 * i];
        ap[i]     = (tok >= 0) ? (g_xh + (size_t)tok * ND + ch * 8) : g_xh;
        abytes[i] = (tok >= 0) ? 16 : 0;
    }
    const __half* bp0 = w1e + (size_t)(n0 + r) * ND + ch * 8;
    const __half* bp1 = w3e + (size_t)(n0 + r) * ND + ch * 8;

    uint32_t sbase = smem_u32(dsm);
    uint32_t dA0 = (uint32_t)(r * RS + ch * 16);
    uint32_t dA1 = (uint32_t)((r + 64) * RS + ch * 16);

    int lane = tid & 31, wid = tid >> 5;
    int wm = wid >> 1, wn = wid & 1;
    int g = lane >> 2, t = lane & 3;

    uint32_t aOff = (uint32_t)((wm * 32 + (lane & 15)) * RS + (lane >> 4) * 16);
    uint32_t bOff = (uint32_t)(((lane & 7) + 8 * (lane >> 4)) * RS + ((lane >> 3) & 1) * 16)
                  + ATILE + (uint32_t)(wn * 32) * RS;

    float acc1[2][4][4], acc3[2][4][4];
#pragma unroll
    for (int mi = 0; mi < 2; mi++)
#pragma unroll
        for (int ni = 0; ni < 4; ni++)
#pragma unroll
            for (int q = 0; q < 4; q++) { acc1[mi][ni][q] = 0.f; acc3[mi][ni][q] = 0.f; }

    const int KT = ND / 32;   // 32

    // prefill stages 0,1,2
#pragma unroll
    for (int p = 0; p < 3; p++) {
        uint32_t st = sbase + p * STAGE;
        int ko = p * 32;
        cpa16(st + dA0, ap[0] + ko, abytes[0]);
        cpa16(st + dA1, ap[1] + ko, abytes[1]);
        cpa16(st + ATILE + dA0, bp0 + ko, 16);
        cpa16(st + ATILE + dA1, bp1 + ko, 16);
        CPA_COMMIT();
    }

    for (int kt = 0; kt < KT; kt++) {
        CPA_WAIT2();
        __syncthreads();
        if (kt + 3 < KT) {
            uint32_t st = sbase + ((kt + 3) & 3) * STAGE;
            int ko = (kt + 3) * 32;
            cpa16(st + dA0, ap[0] + ko, abytes[0]);
            cpa16(st + dA1, ap[1] + ko, abytes[1]);
            cpa16(st + ATILE + dA0, bp0 + ko, 16);
            cpa16(st + ATILE + dA1, bp1 + ko, 16);
        }
        CPA_COMMIT();

        uint32_t st = sbase + (kt & 3) * STAGE;
        uint32_t aAddr = st + aOff;
        uint32_t bAddr = st + bOff;
#pragma unroll
        for (int kc = 0; kc < 2; kc++) {
            uint32_t kb = kc * 32;
            uint32_t af[2][4], bf1[2][4], bf3[2][4];
            ldsm_x4(af[0], aAddr + kb);
            ldsm_x4(af[1], aAddr + kb + 16 * RS);
            ldsm_x4(bf1[0], bAddr + kb);
            ldsm_x4(bf1[1], bAddr + kb + 16 * RS);
            ldsm_x4(bf3[0], bAddr + kb + 64 * RS);
            ldsm_x4(bf3[1], bAddr + kb + 80 * RS);
#pragma unroll
            for (int mi = 0; mi < 2; mi++)
#pragma unroll
                for (int j = 0; j < 4; j++) {
                    mma_f16(acc1[mi][j], af[mi], &bf1[j >> 1][2 * (j & 1)]);
                    mma_f16(acc3[mi][j], af[mi], &bf3[j >> 1][2 * (j & 1)]);
                }
        }
    }

    // epilogue: silu(acc1)*acc3 -> half2 -> g_h
#pragma unroll
    for (int mi = 0; mi < 2; mi++) {
#pragma unroll
        for (int hf = 0; hf < 2; hf++) {
            int mrow = wm * 32 + mi * 16 + g + hf * 8;
            int m = m0 + mrow;
            if (m >= cnt) continue;
            size_t rr = (size_t)(off + m);
#pragma unroll
            for (int ni = 0; ni < 4; ni++) {
                float a0 = acc1[mi][ni][hf * 2 + 0];
                float a1 = acc1[mi][ni][hf * 2 + 1];
                float v0 = __fdividef(a0, 1.f + __expf(-a0)) * acc3[mi][ni][hf * 2 + 0];
                float v1 = __fdividef(a1, 1.f + __expf(-a1)) * acc3[mi][ni][hf * 2 + 1];
                int col = n0 + wn * 32 + ni * 8 + 2 * t;
                *(__half2*)(g_h + rr * NH + col) = __floats2half2_rn(v0, v1);
            }
        }
    }
}

// ---------------------------------------------------------------------------
// GEMM2: g_h[128, 2816] @ w2h[128, 2816]^T * pw -> atomicAdd out
// grid (8, MAXTILES): x = n-tile (fastest -> A-slice L2 reuse), y = m-tile
// ---------------------------------------------------------------------------
__global__ __launch_bounds__(256, 2) void gemm2_kernel(float* __restrict__ out) {
    extern __shared__ char dsm[];

    int bt = blockIdx.y;
    if (bt >= g_ntiles) return;
    int e   = g_tile_e[bt];
    int m0  = g_tile_m0[bt];
    int cnt = g_counts[e];
    int n0  = blockIdx.x * 128;
    int off = g_offsets[e];

    int tid = threadIdx.x;
    const __half* w2e = g_w2h + (size_t)e * ND * NH;

    int r  = tid >> 2;
    int ch = tid & 3;
    const __half* ap[2]; int abytes[2];
#pragma unroll
    for (int i = 0; i < 2; i++) {
        bool valid = (m0 + r + 64 * i) < cnt;
        ap[i]     = valid ? (g_h + (size_t)(off + m0 + r + 64 * i) * NH + ch * 8) : g_h;
        abytes[i] = valid ? 16 : 0;
    }
    const __half* bp[2];
#pragma unroll
    for (int i = 0; i < 2; i++)
        bp[i] = w2e + (size_t)(n0 + r + 64 * i) * NH + ch * 8;

    uint32_t sbase = smem_u32(dsm);
    uint32_t dA0 = (uint32_t)(r * RS + ch * 16);
    uint32_t dA1 = (uint32_t)((r + 64) * RS + ch * 16);

    int lane = tid & 31, wid = tid >> 5;
    int wm = wid >> 2, wn = wid & 3;
    int g = lane >> 2, t = lane & 3;

    uint32_t aOff = (uint32_t)((wm * 64 + (lane & 15)) * RS + (lane >> 4) * 16);
    uint32_t bOff = (uint32_t)(((lane & 7) + 8 * (lane >> 4)) * RS + ((lane >> 3) & 1) * 16)
                  + ATILE + (uint32_t)(wn * 32) * RS;

    float acc[4][4][4];
#pragma unroll
    for (int mi = 0; mi < 4; mi++)
#pragma unroll
        for (int ni = 0; ni < 4; ni++)
#pragma unroll
            for (int q = 0; q < 4; q++) acc[mi][ni][q] = 0.f;

    const int KT = NH / 32;   // 88

#pragma unroll
    for (int p = 0; p < 3; p++) {
        uint32_t st = sbase + p * STAGE;
        int ko = p * 32;
        cpa16(st + dA0, ap[0] + ko, abytes[0]);
        cpa16(st + dA1, ap[1] + ko, abytes[1]);
        cpa16(st + ATILE + dA0, bp[0] + ko, 16);
        cpa16(st + ATILE + dA1, bp[1] + ko, 16);
        CPA_COMMIT();
    }

    for (int kt = 0; kt < KT; kt++) {
        CPA_WAIT2();
        __syncthreads();
        if (kt + 3 < KT) {
            uint32_t st = sbase + ((kt + 3) & 3) * STAGE;
            int ko = (kt + 3) * 32;
            cpa16(st + dA0, ap[0] + ko, abytes[0]);
            cpa16(st + dA1, ap[1] + ko, abytes[1]);
            cpa16(st + ATILE + dA0, bp[0] + ko, 16);
            cpa16(st + ATILE + dA1, bp[1] + ko, 16);
        }
        CPA_COMMIT();

        uint32_t st = sbase + (kt & 3) * STAGE;
        uint32_t aAddr = st + aOff;
        uint32_t bAddr = st + bOff;
#pragma unroll
        for (int kc = 0; kc < 2; kc++) {
            uint32_t kb = kc * 32;
            uint32_t af[4][4], bf[2][4];
#pragma unroll
            for (int mi = 0; mi < 4; mi++)
                ldsm_x4(af[mi], aAddr + kb + (uint32_t)(mi * 16) * RS);
            ldsm_x4(bf[0], bAddr + kb);
            ldsm_x4(bf[1], bAddr + kb + 16 * RS);
#pragma unroll
            for (int mi = 0; mi < 4; mi++)
#pragma unroll
                for (int j = 0; j < 4; j++)
                    mma_f16(acc[mi][j], af[mi], &bf[j >> 1][2 * (j & 1)]);
        }
    }

    // epilogue: scale by combine weight, atomicAdd into out
#pragma unroll
    for (int mi = 0; mi < 4; mi++) {
#pragma unroll
        for (int hf = 0; hf < 2; hf++) {
            int mrow = wm * 64 + mi * 16 + g + hf * 8;
            int m = m0 + mrow;
            if (m >= cnt) continue;
            int rr = off + m;
            int tok = g_perm[rr];
            float w = g_pw[rr];
            float* orow = out + (size_t)tok * ND;
#pragma unroll
            for (int ni = 0; ni < 4; ni++) {
                int col = n0 + wn * 32 + ni * 8 + 2 * t;
                atomicAdd(orow + col,     w * acc[mi][ni][hf * 2 + 0]);
                atomicAdd(orow + col + 1, w * acc[mi][ni][hf * 2 + 1]);
            }
        }
    }
}

// ---------------------------------------------------------------------------
extern "C" void kernel_launch(void* const* d_in, const int* in_sizes, int n_in,
                              void* d_out, int out_size) {
    const float* x  = (const float*)d_in[0];
    const float* gw = (const float*)d_in[1];
    const float* w1 = (const float*)d_in[2];
    const float* w2 = (const float*)d_in[3];
    const float* w3 = (const float*)d_in[4];
    float* out = (float*)d_out;

    cudaFuncSetAttribute(gemm1_kernel, cudaFuncAttributeMaxDynamicSharedMemorySize, GSMEM);
    cudaFuncSetAttribute(gemm2_kernel, cudaFuncAttributeMaxDynamicSharedMemorySize, GSMEM);

    dim3 pg(8192, 4);   // y=0: x+router (first), y=1..3: w1/w3/w2 grid-stride
    prep_kernel<<<pg, 256>>>((const float4*)x, gw, (const float4*)w1,
                             (const float4*)w2, (const float4*)w3, (float4*)out);
    scan_kernel<<<1, 256>>>();
    scatter_kernel<<<(NROWS + 255) / 256, 256>>>();

    dim3 g1(MAXTILES, NH / 64);     // compact m-tiles fastest; (144, 44)
    gemm1_kernel<<<g1, 256, GSMEM>>>();

    dim3 g2(ND / 128, MAXTILES);    // n fastest; (8, 144)
    gemm2_kernel<<<g2, 256, GSMEM>>>(out);
}

// round 17
// speedup vs baseline: 1.4708x; 1.0105x over previous
#include <cuda_runtime.h>
#include <cuda_fp16.h>
#include <math.h>
#include <stdint.h>

#define NT 8192          // tokens (B*S)
#define ND 1024          // model dim
#define NE 8             // experts
#define NH 2816          // hidden dim
#define NROWS (NT * 2)   // total (token, expert-slot) rows
#define WELEM (NE * NH * ND)
#define NW4 (WELEM / 4)          // 5,767,168
#define NX4 (NT * ND / 4)        // 2,097,152 == 8192*256 exactly
#define MAXTILES 144

// ---- device scratch (allocation-free) ----
__device__ int    g_counts[NE];
__device__ int    g_ctr[NE];
__device__ int    g_offsets[NE];
__device__ int    g_route_e[NROWS];
__device__ float  g_route_w[NROWS];
__device__ int    g_perm[NROWS];
__device__ float  g_pw[NROWS];
__device__ int    g_ntiles;
__device__ int    g_tile_e[MAXTILES];
__device__ int    g_tile_m0[MAXTILES];
__device__ __half g_h[(size_t)NROWS * NH];
__device__ __half g_xh[(size_t)NT * ND];
__device__ __half g_w1h[(size_t)WELEM];
__device__ __half g_w3h[(size_t)WELEM];
__device__ __half g_w2h[(size_t)WELEM];

// ---------------------------------------------------------------------------
// helpers
// ---------------------------------------------------------------------------
__device__ __forceinline__ uint32_t smem_u32(const void* p) {
    uint32_t a;
    asm("{ .reg .u64 t; cvta.to.shared.u64 t, %1; cvt.u32.u64 %0, t; }" : "=r"(a) : "l"(p));
    return a;
}
__device__ __forceinline__ void mma_f16(float c[4], const uint32_t a[4], const uint32_t b[2]) {
    asm volatile(
        "mma.sync.aligned.m16n8k16.row.col.f32.f16.f16.f32 "
        "{%0,%1,%2,%3},{%4,%5,%6,%7},{%8,%9},{%0,%1,%2,%3};\n"
        : "+f"(c[0]), "+f"(c[1]), "+f"(c[2]), "+f"(c[3])
        : "r"(a[0]), "r"(a[1]), "r"(a[2]), "r"(a[3]), "r"(b[0]), "r"(b[1]));
}
__device__ __forceinline__ void ldsm_x4(uint32_t r[4], uint32_t addr) {
    asm volatile("ldmatrix.sync.aligned.m8n8.x4.shared.b16 {%0,%1,%2,%3}, [%4];"
        : "=r"(r[0]), "=r"(r[1]), "=r"(r[2]), "=r"(r[3]) : "r"(addr));
}
__device__ __forceinline__ void cpa16(uint32_t dst, const void* src, int bytes) {
    asm volatile("cp.async.cg.shared.global [%0], [%1], 16, %2;"
        :: "r"(dst), "l"(src), "r"(bytes) : "memory");
}
#define CPA_COMMIT() asm volatile("cp.async.commit_group;" ::: "memory")
#define CPA_WAIT2()  asm volatile("cp.async.wait_group 2;" ::: "memory")

// ---------------------------------------------------------------------------
// prep: one launch, 3 regions (w2 conversion moved into gemm1's first wave).
//   y==0: x fp32->fp16, zero out; blocks 0..1023 additionally run the router
//   y==1/2: w1/w3 fp32->fp16 (grid-stride)
// ---------------------------------------------------------------------------
__global__ void prep_kernel(const float4* __restrict__ x,
                            const float*  __restrict__ gwf,
                            const float4* __restrict__ w1,
                            const float4* __restrict__ w3,
                            float4* __restrict__ out) {
    __shared__ float sg[NE * ND];
    int tid  = threadIdx.x;
    int rgn  = blockIdx.y;
    int base = blockIdx.x * 256 + tid;

    if (rgn == 0) {
        {
            float4 v = x[base];
            out[base] = make_float4(0.f, 0.f, 0.f, 0.f);
            __half2 h0 = __floats2half2_rn(v.x, v.y);
            __half2 h1 = __floats2half2_rn(v.z, v.w);
            ((uint2*)g_xh)[base] = make_uint2(*(uint32_t*)&h0, *(uint32_t*)&h1);
        }
        if (blockIdx.x >= 1024) return;

        // ---- router (exact fp32, identical math to previous rounds) ----
        for (int i = tid; i < NE * ND / 4; i += 256)
            ((float4*)sg)[i] = ((const float4*)gwf)[i];
        __syncthreads();

        int lane = tid & 31;
        int t = blockIdx.x * 8 + (tid >> 5);

        const float4* xv = (const float4*)((const float*)x + (size_t)t * ND);
        float acc[NE];
#pragma unroll
        for (int e = 0; e < NE; e++) acc[e] = 0.f;
#pragma unroll
        for (int j = 0; j < ND / 128; j++) {
            int v = j * 32 + lane;
            float4 xx = xv[v];
#pragma unroll
            for (int e = 0; e < NE; e++) {
                float4 gg = ((const float4*)sg)[e * (ND / 4) + v];
                acc[e] += xx.x * gg.x + xx.y * gg.y + xx.z * gg.z + xx.w * gg.w;
            }
        }
#pragma unroll
        for (int e = 0; e < NE; e++)
#pragma unroll
            for (int o = 16; o > 0; o >>= 1)
                acc[e] += __shfl_xor_sync(0xffffffffu, acc[e], o);

        if (lane == 0) {
            int b0 = 0;
#pragma unroll
            for (int e = 1; e < NE; e++) if (acc[e] > acc[b0]) b0 = e;
            int b1 = (b0 == 0) ? 1 : 0;
#pragma unroll
            for (int e = 0; e < NE; e++)
                if (e != b0 && acc[e] > acc[b1]) b1 = e;
            float d  = acc[b1] - acc[b0];
            float e1 = expf(d);
            float s  = 1.f + e1;
            g_route_e[2 * t]     = b0;  g_route_w[2 * t]     = 1.f / s;
            g_route_e[2 * t + 1] = b1;  g_route_w[2 * t + 1] = e1 / s;
        }
        return;
    }

    const float4* src = (rgn == 1) ? w1 : w3;
    uint2* dst = (rgn == 1) ? (uint2*)g_w1h : (uint2*)g_w3h;
    for (int i = base; i < NW4; i += 8192 * 256) {
        float4 v = src[i];
        __half2 h0 = __floats2half2_rn(v.x, v.y);
        __half2 h1 = __floats2half2_rn(v.z, v.w);
        dst[i] = make_uint2(*(uint32_t*)&h0, *(uint32_t*)&h1);
    }
}

// ---------------------------------------------------------------------------
// scan: one block; histogram of route_e -> counts/offsets, zero g_ctr,
// and build the compact active-tile table (<=135 tiles of 128 rows)
// ---------------------------------------------------------------------------
__global__ void scan_kernel() {
    __shared__ int h[NE];
    int tid = threadIdx.x;
    if (tid < NE) h[tid] = 0;
    __syncthreads();
    for (int i = tid; i < NROWS; i += 256)
        atomicAdd(&h[g_route_e[i]], 1);
    __syncthreads();
    if (tid == 0) {
        int o = 0, nt = 0;
        for (int e = 0; e < NE; e++) {
            int c = h[e];
            g_counts[e] = c;
            g_offsets[e] = o;
            o += c;
            g_ctr[e] = 0;
            for (int m0 = 0; m0 < c; m0 += 128) {
                g_tile_e[nt]  = e;
                g_tile_m0[nt] = m0;
                nt++;
            }
        }
        g_ntiles = nt;
    }
}

__global__ void scatter_kernel() {
    int i = blockIdx.x * blockDim.x + threadIdx.x;
    if (i >= NROWS) return;
    int e = g_route_e[i];
    int p = atomicAdd(&g_ctr[e], 1);
    int r = g_offsets[e] + p;
    g_perm[r] = i >> 1;
    g_pw[r]   = g_route_w[i];
}

// ---------------------------------------------------------------------------
// GEMM geometry: BK=32 halves, row stride 80 B, FOUR cp.async stages
// ---------------------------------------------------------------------------
#define RS    80
#define ATILE (128 * RS)            // 10240 B
#define STAGE (2 * ATILE)           // 20480 B
#define GSMEM (4 * STAGE)           // 81920 B dynamic; x2 CTA = 160 KB < 228 KB

// ---------------------------------------------------------------------------
// GEMM1: xh[gathered 128, 1024] @ {w1h,w3h}[64,1024]^T -> silu-gate -> g_h
// grid (MAXTILES, 45): y==0 -> w2 fp32->fp16 converter slice (first wave,
// hides under gemm1's idle DRAM; stream order makes w2h ready for gemm2);
// y>=1 -> compute tile with n0 = (y-1)*64. x = compact m-tile (fastest).
// ---------------------------------------------------------------------------
__global__ __launch_bounds__(256, 2) void gemm1_kernel(const float4* __restrict__ w2) {
    extern __shared__ char dsm[];
    __shared__ int stok[128];

    if (blockIdx.y == 0) {
        // ---- w2 converter slice: 144 blocks x 256 threads, grid-stride ----
        int base = blockIdx.x * 256 + threadIdx.x;
        uint2* dst = (uint2*)g_w2h;
        for (int i = base; i < NW4; i += MAXTILES * 256) {
            float4 v = w2[i];
            __half2 h0 = __floats2half2_rn(v.x, v.y);
            __half2 h1 = __floats2half2_rn(v.z, v.w);
            dst[i] = make_uint2(*(uint32_t*)&h0, *(uint32_t*)&h1);
        }
        return;
    }

    int bx = blockIdx.x;
    if (bx >= g_ntiles) return;
    int e   = g_tile_e[bx];
    int m0  = g_tile_m0[bx];
    int cnt = g_counts[e];
    int n0  = (blockIdx.y - 1) * 64;
    int off = g_offsets[e];

    int tid = threadIdx.x;
    if (tid < 128)
        stok[tid] = (m0 + tid < cnt) ? g_perm[off + m0 + tid] : -1;
    __syncthreads();

    const __half* w1e = g_w1h + (size_t)e * NH * ND;
    const __half* w3e = g_w3h + (size_t)e * NH * ND;

    int r  = tid >> 2;          // 0..63
    int ch = tid & 3;           // 16B chunk
    const __half* ap[2]; int abytes[2];
#pragma unroll
    for (int i = 0; i < 2; i++) {
        int tok = stok[r + 64 * i];
        ap[i]     = (tok >= 0) ? (g_xh + (size_t)tok * ND + ch * 8) : g_xh;
        abytes[i] = (tok >= 0) ? 16 : 0;
    }
    const __half* bp0 = w1e + (size_t)(n0 + r) * ND + ch * 8;
    const __half* bp1 = w3e + (size_t)(n0 + r) * ND + ch * 8;

    uint32_t sbase = smem_u32(dsm);
    uint32_t dA0 = (uint32_t)(r * RS + ch * 16);
    uint32_t dA1 = (uint32_t)((r + 64) * RS + ch * 16);

    int lane = tid & 31, wid = tid >> 5;
    int wm = wid >> 1, wn = wid & 1;
    int g = lane >> 2, t = lane & 3;

    uint32_t aOff = (uint32_t)((wm * 32 + (lane & 15)) * RS + (lane >> 4) * 16);
    uint32_t bOff = (uint32_t)(((lane & 7) + 8 * (lane >> 4)) * RS + ((lane >> 3) & 1) * 16)
                  + ATILE + (uint32_t)(wn * 32) * RS;

    float acc1[2][4][4], acc3[2][4][4];
#pragma unroll
    for (int mi = 0; mi < 2; mi++)
#pragma unroll
        for (int ni = 0; ni < 4; ni++)
#pragma unroll
            for (int q = 0; q < 4; q++) { acc1[mi][ni][q] = 0.f; acc3[mi][ni][q] = 0.f; }

    const int KT = ND / 32;   // 32

    // prefill stages 0,1,2
#pragma unroll
    for (int p = 0; p < 3; p++) {
        uint32_t st = sbase + p * STAGE;
        int ko = p * 32;
        cpa16(st + dA0, ap[0] + ko, abytes[0]);
        cpa16(st + dA1, ap[1] + ko, abytes[1]);
        cpa16(st + ATILE + dA0, bp0 + ko, 16);
        cpa16(st + ATILE + dA1, bp1 + ko, 16);
        CPA_COMMIT();
    }

    for (int kt = 0; kt < KT; kt++) {
        CPA_WAIT2();
        __syncthreads();
        if (kt + 3 < KT) {
            uint32_t st = sbase + ((kt + 3) & 3) * STAGE;
            int ko = (kt + 3) * 32;
            cpa16(st + dA0, ap[0] + ko, abytes[0]);
            cpa16(st + dA1, ap[1] + ko, abytes[1]);
            cpa16(st + ATILE + dA0, bp0 + ko, 16);
            cpa16(st + ATILE + dA1, bp1 + ko, 16);
        }
        CPA_COMMIT();

        uint32_t st = sbase + (kt & 3) * STAGE;
        uint32_t aAddr = st + aOff;
        uint32_t bAddr = st + bOff;
#pragma unroll
        for (int kc = 0; kc < 2; kc++) {
            uint32_t kb = kc * 32;
            uint32_t af[2][4], bf1[2][4], bf3[2][4];
            ldsm_x4(af[0], aAddr + kb);
            ldsm_x4(af[1], aAddr + kb + 16 * RS);
            ldsm_x4(bf1[0], bAddr + kb);
            ldsm_x4(bf1[1], bAddr + kb + 16 * RS);
            ldsm_x4(bf3[0], bAddr + kb + 64 * RS);
            ldsm_x4(bf3[1], bAddr + kb + 80 * RS);
#pragma unroll
            for (int mi = 0; mi < 2; mi++)
#pragma unroll
                for (int j = 0; j < 4; j++) {
                    mma_f16(acc1[mi][j], af[mi], &bf1[j >> 1][2 * (j & 1)]);
                    mma_f16(acc3[mi][j], af[mi], &bf3[j >> 1][2 * (j & 1)]);
                }
        }
    }

    // epilogue: silu(acc1)*acc3 -> half2 -> g_h
#pragma unroll
    for (int mi = 0; mi < 2; mi++) {
#pragma unroll
        for (int hf = 0; hf < 2; hf++) {
            int mrow = wm * 32 + mi * 16 + g + hf * 8;
            int m = m0 + mrow;
            if (m >= cnt) continue;
            size_t rr = (size_t)(off + m);
#pragma unroll
            for (int ni = 0; ni < 4; ni++) {
                float a0 = acc1[mi][ni][hf * 2 + 0];
                float a1 = acc1[mi][ni][hf * 2 + 1];
                float v0 = __fdividef(a0, 1.f + __expf(-a0)) * acc3[mi][ni][hf * 2 + 0];
                float v1 = __fdividef(a1, 1.f + __expf(-a1)) * acc3[mi][ni][hf * 2 + 1];
                int col = n0 + wn * 32 + ni * 8 + 2 * t;
                *(__half2*)(g_h + rr * NH + col) = __floats2half2_rn(v0, v1);
            }
        }
    }
}

// ---------------------------------------------------------------------------
// GEMM2: g_h[128, 2816] @ w2h[128, 2816]^T * pw -> atomicAdd out
// grid (8, MAXTILES): x = n-tile (fastest -> A-slice L2 reuse), y = m-tile
// ---------------------------------------------------------------------------
__global__ __launch_bounds__(256, 2) void gemm2_kernel(float* __restrict__ out) {
    extern __shared__ char dsm[];

    int bt = blockIdx.y;
    if (bt >= g_ntiles) return;
    int e   = g_tile_e[bt];
    int m0  = g_tile_m0[bt];
    int cnt = g_counts[e];
    int n0  = blockIdx.x * 128;
    int off = g_offsets[e];

    int tid = threadIdx.x;
    const __half* w2e = g_w2h + (size_t)e * ND * NH;

    int r  = tid >> 2;
    int ch = tid & 3;
    const __half* ap[2]; int abytes[2];
#pragma unroll
    for (int i = 0; i < 2; i++) {
        bool valid = (m0 + r + 64 * i) < cnt;
        ap[i]     = valid ? (g_h + (size_t)(off + m0 + r + 64 * i) * NH + ch * 8) : g_h;
        abytes[i] = valid ? 16 : 0;
    }
    const __half* bp[2];
#pragma unroll
    for (int i = 0; i < 2; i++)
        bp[i] = w2e + (size_t)(n0 + r + 64 * i) * NH + ch * 8;

    uint32_t sbase = smem_u32(dsm);
    uint32_t dA0 = (uint32_t)(r * RS + ch * 16);
    uint32_t dA1 = (uint32_t)((r + 64) * RS + ch * 16);

    int lane = tid & 31, wid = tid >> 5;
    int wm = wid >> 2, wn = wid & 3;
    int g = lane >> 2, t = lane & 3;

    uint32_t aOff = (uint32_t)((wm * 64 + (lane & 15)) * RS + (lane >> 4) * 16);
    uint32_t bOff = (uint32_t)(((lane & 7) + 8 * (lane >> 4)) * RS + ((lane >> 3) & 1) * 16)
                  + ATILE + (uint32_t)(wn * 32) * RS;

    float acc[4][4][4];
#pragma unroll
    for (int mi = 0; mi < 4; mi++)
#pragma unroll
        for (int ni = 0; ni < 4; ni++)
#pragma unroll
            for (int q = 0; q < 4; q++) acc[mi][ni][q] = 0.f;

    const int KT = NH / 32;   // 88

#pragma unroll
    for (int p = 0; p < 3; p++) {
        uint32_t st = sbase + p * STAGE;
        int ko = p * 32;
        cpa16(st + dA0, ap[0] + ko, abytes[0]);
        cpa16(st + dA1, ap[1] + ko, abytes[1]);
        cpa16(st + ATILE + dA0, bp[0] + ko, 16);
        cpa16(st + ATILE + dA1, bp[1] + ko, 16);
        CPA_COMMIT();
    }

    for (int kt = 0; kt < KT; kt++) {
        CPA_WAIT2();
        __syncthreads();
        if (kt + 3 < KT) {
            uint32_t st = sbase + ((kt + 3) & 3) * STAGE;
            int ko = (kt + 3) * 32;
            cpa16(st + dA0, ap[0] + ko, abytes[0]);
            cpa16(st + dA1, ap[1] + ko, abytes[1]);
            cpa16(st + ATILE + dA0, bp[0] + ko, 16);
            cpa16(st + ATILE + dA1, bp[1] + ko, 16);
        }
        CPA_COMMIT();

        uint32_t st = sbase + (kt & 3) * STAGE;
        uint32_t aAddr = st + aOff;
        uint32_t bAddr = st + bOff;
#pragma unroll
        for (int kc = 0; kc < 2; kc++) {
            uint32_t kb = kc * 32;
            uint32_t af[4][4], bf[2][4];
#pragma unroll
            for (int mi = 0; mi < 4; mi++)
                ldsm_x4(af[mi], aAddr + kb + (uint32_t)(mi * 16) * RS);
            ldsm_x4(bf[0], bAddr + kb);
            ldsm_x4(bf[1], bAddr + kb + 16 * RS);
#pragma unroll
            for (int mi = 0; mi < 4; mi++)
#pragma unroll
                for (int j = 0; j < 4; j++)
                    mma_f16(acc[mi][j], af[mi], &bf[j >> 1][2 * (j & 1)]);
        }
    }

    // epilogue: scale by combine weight, atomicAdd into out
#pragma unroll
    for (int mi = 0; mi < 4; mi++) {
#pragma unroll
        for (int hf = 0; hf < 2; hf++) {
            int mrow = wm * 64 + mi * 16 + g + hf * 8;
            int m = m0 + mrow;
            if (m >= cnt) continue;
            int rr = off + m;
            int tok = g_perm[rr];
            float w = g_pw[rr];
            float* orow = out + (size_t)tok * ND;
#pragma unroll
            for (int ni = 0; ni < 4; ni++) {
                int col = n0 + wn * 32 + ni * 8 + 2 * t;
                atomicAdd(orow + col,     w * acc[mi][ni][hf * 2 + 0]);
                atomicAdd(orow + col + 1, w * acc[mi][ni][hf * 2 + 1]);
            }
        }
    }
}

// ---------------------------------------------------------------------------
extern "C" void kernel_launch(void* const* d_in, const int* in_sizes, int n_in,
                              void* d_out, int out_size) {
    const float* x  = (const float*)d_in[0];
    const float* gw = (const float*)d_in[1];
    const float* w1 = (const float*)d_in[2];
    const float* w2 = (const float*)d_in[3];
    const float* w3 = (const float*)d_in[4];
    float* out = (float*)d_out;

    cudaFuncSetAttribute(gemm1_kernel, cudaFuncAttributeMaxDynamicSharedMemorySize, GSMEM);
    cudaFuncSetAttribute(gemm2_kernel, cudaFuncAttributeMaxDynamicSharedMemorySize, GSMEM);

    dim3 pg(8192, 3);   // y=0: x+router, y=1: w1, y=2: w3 (w2 converts inside gemm1)
    prep_kernel<<<pg, 256>>>((const float4*)x, gw, (const float4*)w1,
                             (const float4*)w3, (float4*)out);
    scan_kernel<<<1, 256>>>();
    scatter_kernel<<<(NROWS + 255) / 256, 256>>>();

    dim3 g1(MAXTILES, NH / 64 + 1);  // y==0: w2 converter slice; y>=1: compute
    gemm1_kernel<<<g1, 256, GSMEM>>>((const float4*)w2);

    dim3 g2(ND / 128, MAXTILES);     // n fastest; (8, 144)
    gemm2_kernel<<<g2, 256, GSMEM>>>(out);
}